// round 13
// baseline (speedup 1.0000x reference)
#include <cuda_runtime.h>
#include <cuda_bf16.h>

#define NN   100000
#define EE   1600000
#define EOUT 400000
#define HIDD 64
#define GB   ((NN + 255) / 256)
#define STATS_BLOCKS 256
#define SCAN_BLOCKS  ((NN + 1023) / 1024)
#define BN_EPS 1e-5f

typedef unsigned long long u64;

// ---------------- f32x2 packed helpers (sm_103a FFMA2 path) ----------------
__device__ __forceinline__ u64 pack2(float x) {
    u64 r; unsigned xi = __float_as_uint(x);
    asm("mov.b64 %0, {%1, %1};" : "=l"(r) : "r"(xi));
    return r;
}
__device__ __forceinline__ u64 fma2(u64 a, u64 b, u64 c) {
    u64 d;
    asm("fma.rn.f32x2 %0, %1, %2, %3;" : "=l"(d) : "l"(a), "l"(b), "l"(c));
    return d;
}
__device__ __forceinline__ u64 add2(u64 a, u64 b) {
    u64 d;
    asm("add.rn.f32x2 %0, %1, %2;" : "=l"(d) : "l"(a), "l"(b));
    return d;
}

// ---------------- scratch (device globals; zero-initialized, no alloc) -----
__device__ float g_dinv[NN];
__device__ int   g_deg[NN];          // holds EXTRA degree; reset to 0 by scan1
__device__ int   g_rowptr[NN + 1];
__device__ int   g_cursor[NN];
__device__ int   g_bsum[SCAN_BLOCKS];
__device__ int2  g_csr[EE];          // (src, norm-bits)
__device__ float g_x  [NN * HIDD];   // x_embed
__device__ float g_hw [NN * HIDD];   // aggregated x (pre-GEMM)
__device__ float g_agg[NN * HIDD];   // conv output
__device__ float g_part[STATS_BLOCKS * 128];
__device__ float g_scale[HIDD];
__device__ float g_shift[HIDD];
__device__ unsigned g_ticket;        // zero-init; last block resets
__device__ float4 g_head[NN];        // (a0,a1,b0,b1) edge-head halves

// ---------------- degree (extra degree on top of self loop) ----------------
// 4 edges per thread, int4 dst reads (EE % 4 == 0)
__global__ void k_deg_count(const int* __restrict__ ei) {
    int t = blockIdx.x * 256 + threadIdx.x;
    if (t >= EE / 4) return;
    int4 d = ((const int4*)(ei + EE))[t];
    atomicAdd(&g_deg[d.x], 1);
    atomicAdd(&g_deg[d.y], 1);
    atomicAdd(&g_deg[d.z], 1);
    atomicAdd(&g_deg[d.w], 1);
}

// ---------------- scan phase 1 (+ dinv fused + deg reset for next replay) --
__global__ void k_scan1() {
    __shared__ int wsum[32];
    int tid = threadIdx.x;               // 1024
    int lane = tid & 31, wid = tid >> 5;
    int i = blockIdx.x * 1024 + tid;
    int v = 0;
    if (i < NN) {
        v = g_deg[i];                    // extra degree = deg - 1
        g_deg[i] = 0;                    // reset for next graph replay
        g_dinv[i] = rsqrtf((float)(v + 1));
    }
    int incl = v;
    #pragma unroll
    for (int o = 1; o < 32; o <<= 1) {
        int t = __shfl_up_sync(0xffffffffu, incl, o);
        if (lane >= o) incl += t;
    }
    if (lane == 31) wsum[wid] = incl;
    __syncthreads();
    if (wid == 0) {
        int s = wsum[lane];
        #pragma unroll
        for (int o = 1; o < 32; o <<= 1) {
            int t = __shfl_up_sync(0xffffffffu, s, o);
            if (lane >= o) s += t;
        }
        wsum[lane] = s;
    }
    __syncthreads();
    int excl = (wid ? wsum[wid - 1] : 0) + incl - v;
    if (i < NN) g_rowptr[i] = excl;      // block-local for now
    if (tid == 1023) g_bsum[blockIdx.x] = wsum[31];   // sole writer
}

// ---- scan phases 2+3 merged: every block re-scans the 98 block sums -------
__global__ void k_scan23() {
    __shared__ int sb[128];
    int tid = threadIdx.x;               // 256
    if (tid < 128) sb[tid] = (tid < SCAN_BLOCKS) ? g_bsum[tid] : 0;
    __syncthreads();
    #pragma unroll
    for (int o = 1; o < 128; o <<= 1) {
        int v = 0;
        if (tid < 128 && tid >= o) v = sb[tid - o];
        __syncthreads();
        if (tid < 128) sb[tid] += v;     // inclusive scan
        __syncthreads();
    }
    int i = blockIdx.x * 256 + tid;
    if (i < NN) {
        int b = i >> 10;
        int off = b ? sb[b - 1] : 0;     // exclusive prefix
        int r = g_rowptr[i] + off;
        g_rowptr[i] = r;
        g_cursor[i] = r;
    }
    if (i == 0) g_rowptr[NN] = EE;       // sum(deg-1) == E exactly
}

// ---------------- CSR fill: 4 edges per thread, int4 reads ----------------
__global__ void k_fill(const int* __restrict__ ei) {
    int t = blockIdx.x * 256 + threadIdx.x;
    if (t >= EE / 4) return;
    int4 s = ((const int4*)ei)[t];
    int4 d = ((const int4*)(ei + EE))[t];
    {
        int p = atomicAdd(&g_cursor[d.x], 1);
        g_csr[p] = make_int2(s.x, __float_as_int(g_dinv[s.x] * g_dinv[d.x]));
    }
    {
        int p = atomicAdd(&g_cursor[d.y], 1);
        g_csr[p] = make_int2(s.y, __float_as_int(g_dinv[s.y] * g_dinv[d.y]));
    }
    {
        int p = atomicAdd(&g_cursor[d.z], 1);
        g_csr[p] = make_int2(s.z, __float_as_int(g_dinv[s.z] * g_dinv[d.z]));
    }
    {
        int p = atomicAdd(&g_cursor[d.w], 1);
        g_csr[p] = make_int2(s.w, __float_as_int(g_dinv[s.w] * g_dinv[d.w]));
    }
}

// ---------------- node embedding: node per thread, f32x2 ----------------
__global__ void __launch_bounds__(256) k_embed(const float* __restrict__ x,
                                               const float* __restrict__ W,
                                               const float* __restrict__ b) {
    __shared__ __align__(16) float Ws[16 * 64];
    __shared__ __align__(16) float bs[64];
    int tid = threadIdx.x;
    for (int i = tid; i < 16 * 64; i += 256) Ws[i] = W[i];
    if (tid < 64) bs[tid] = b[tid];
    __syncthreads();
    int n = blockIdx.x * 256 + tid;
    if (n >= NN) return;
    u64 acc2[32];
    const u64* b2 = (const u64*)bs;
    #pragma unroll
    for (int h = 0; h < 32; h++) acc2[h] = b2[h];
    const float4* x4 = (const float4*)(x + (size_t)n * 16);
    #pragma unroll
    for (int k4 = 0; k4 < 4; k4++) {
        float4 xv = x4[k4];
        #pragma unroll
        for (int kk = 0; kk < 4; kk++) {
            u64 xx = pack2((&xv.x)[kk]);
            const ulonglong2* wrow = (const ulonglong2*)(Ws + (k4 * 4 + kk) * 64);
            #pragma unroll
            for (int h4 = 0; h4 < 16; h4++) {
                ulonglong2 w = wrow[h4];
                acc2[2 * h4]     = fma2(xx, w.x, acc2[2 * h4]);
                acc2[2 * h4 + 1] = fma2(xx, w.y, acc2[2 * h4 + 1]);
            }
        }
    }
    ulonglong2* o2 = (ulonglong2*)(g_x + (size_t)n * 64);
    #pragma unroll
    for (int h4 = 0; h4 < 16; h4++) {
        ulonglong2 o; o.x = acc2[2 * h4]; o.y = acc2[2 * h4 + 1];
        o2[h4] = o;
    }
}

// ---------------- gather: hw[n] = sum nrm*x[src] + dinv^2*x[n] --------------
__global__ void k_gather() {
    int t = blockIdx.x * 256 + threadIdx.x;
    int node = t >> 5;
    if (node >= NN) return;
    int lane = t & 31;
    const float2* x2 = (const float2*)g_x;
    int beg = g_rowptr[node], end = g_rowptr[node + 1];
    float di = g_dinv[node];
    float2 acc = x2[node * 32 + lane];
    acc.x *= di * di; acc.y *= di * di;
    float2 acc2 = make_float2(0.f, 0.f);
    int i = beg;
    if ((i & 1) && i < end) {            // align to int4 boundary
        int2 a = g_csr[i];
        float2 va = x2[a.x * 32 + lane];
        float na = __int_as_float(a.y);
        acc.x = fmaf(na, va.x, acc.x); acc.y = fmaf(na, va.y, acc.y);
        i++;
    }
    for (; i + 3 < end; i += 4) {        // 4 independent gathers in flight
        int4 c0 = *(const int4*)&g_csr[i];
        int4 c1 = *(const int4*)&g_csr[i + 2];
        float2 v0 = x2[c0.x * 32 + lane];
        float2 v1 = x2[c0.z * 32 + lane];
        float2 v2 = x2[c1.x * 32 + lane];
        float2 v3 = x2[c1.z * 32 + lane];
        float n0 = __int_as_float(c0.y), n1 = __int_as_float(c0.w);
        float n2 = __int_as_float(c1.y), n3 = __int_as_float(c1.w);
        acc.x  = fmaf(n0, v0.x, acc.x);  acc.y  = fmaf(n0, v0.y, acc.y);
        acc2.x = fmaf(n1, v1.x, acc2.x); acc2.y = fmaf(n1, v1.y, acc2.y);
        acc.x  = fmaf(n2, v2.x, acc.x);  acc.y  = fmaf(n2, v2.y, acc.y);
        acc2.x = fmaf(n3, v3.x, acc2.x); acc2.y = fmaf(n3, v3.y, acc2.y);
    }
    for (; i < end; i++) {
        int2 a = g_csr[i];
        float2 va = x2[a.x * 32 + lane];
        float na = __int_as_float(a.y);
        acc.x = fmaf(na, va.x, acc.x); acc.y = fmaf(na, va.y, acc.y);
    }
    acc.x += acc2.x; acc.y += acc2.y;
    ((float2*)g_hw)[node * 32 + lane] = acc;
}

// ---------------- GEMM: agg = hw @ W + b (node per thread, f32x2) ----------
__global__ void __launch_bounds__(256) k_gemm(const float* __restrict__ W,
                                              const float* __restrict__ b) {
    __shared__ __align__(16) float Ws[64 * 64];
    __shared__ __align__(16) float bs[64];
    int tid = threadIdx.x;               // 256
    for (int i = tid; i < 64 * 64; i += 256) Ws[i] = W[i];
    if (tid < 64) bs[tid] = b[tid];
    __syncthreads();
    int n = blockIdx.x * 256 + tid;
    if (n >= NN) return;
    u64 acc2[32];
    #pragma unroll
    for (int h = 0; h < 32; h++) acc2[h] = 0ull;
    const float4* x4 = (const float4*)(g_hw + (size_t)n * 64);
    for (int k4 = 0; k4 < 16; k4++) {
        float4 xk = x4[k4];
        #pragma unroll
        for (int kk = 0; kk < 4; kk++) {
            u64 xx = pack2((&xk.x)[kk]);
            const ulonglong2* wrow = (const ulonglong2*)(Ws + (k4 * 4 + kk) * 64);
            #pragma unroll
            for (int h4 = 0; h4 < 16; h4++) {
                ulonglong2 w = wrow[h4];
                acc2[2 * h4]     = fma2(xx, w.x, acc2[2 * h4]);
                acc2[2 * h4 + 1] = fma2(xx, w.y, acc2[2 * h4 + 1]);
            }
        }
    }
    const u64* b2 = (const u64*)bs;
    ulonglong2* o2 = (ulonglong2*)(g_agg + (size_t)n * 64);
    #pragma unroll
    for (int h4 = 0; h4 < 16; h4++) {
        ulonglong2 o;
        o.x = add2(acc2[2 * h4],     b2[2 * h4]);
        o.y = add2(acc2[2 * h4 + 1], b2[2 * h4 + 1]);
        o2[h4] = o;
    }
}

// --------- BN stats (256 blocks, float4 loads) + fused finalize -------------
__global__ void k_stats(const float* __restrict__ gamma,
                        const float* __restrict__ beta) {
    __shared__ float ssum[16][64];
    __shared__ float ssq [16][64];
    __shared__ float sh[128];
    __shared__ int lastflag;
    int t = threadIdx.x;                 // 256
    int fq = t & 15;                     // float4 column (features fq*4..fq*4+3)
    int ng = t >> 4;                     // node group 0..15
    const float4* a4 = (const float4*)g_agg;
    float4 s = make_float4(0.f, 0.f, 0.f, 0.f);
    float4 q = make_float4(0.f, 0.f, 0.f, 0.f);
    #pragma unroll 4
    for (int n = blockIdx.x * 16 + ng; n < NN; n += STATS_BLOCKS * 16) {
        float4 a = a4[n * 16 + fq];
        s.x += a.x; s.y += a.y; s.z += a.z; s.w += a.w;
        q.x = fmaf(a.x, a.x, q.x); q.y = fmaf(a.y, a.y, q.y);
        q.z = fmaf(a.z, a.z, q.z); q.w = fmaf(a.w, a.w, q.w);
    }
    ((float4*)ssum[ng])[fq] = s;
    ((float4*)ssq [ng])[fq] = q;
    __syncthreads();
    if (t < 64) {
        float a = 0.f;
        #pragma unroll
        for (int g = 0; g < 16; g++) a += ssum[g][t];
        g_part[blockIdx.x * 128 + t] = a;
    } else if (t < 128) {
        int f = t - 64;
        float a = 0.f;
        #pragma unroll
        for (int g = 0; g < 16; g++) a += ssq[g][f];
        g_part[blockIdx.x * 128 + 64 + f] = a;
    }
    __threadfence();
    if (t == 0) lastflag = (atomicAdd(&g_ticket, 1u) == STATS_BLOCKS - 1);
    __syncthreads();
    if (lastflag) {
        if (t < 128) {
            float acc = 0.f;
            #pragma unroll 4
            for (int i = 0; i < STATS_BLOCKS; i++) acc += g_part[i * 128 + t];
            sh[t] = acc;
        }
        __syncthreads();
        if (t < 64) {
            float mean = sh[t] * (1.0f / NN);
            float var  = sh[64 + t] * (1.0f / NN) - mean * mean;
            float sc   = gamma[t] * rsqrtf(var + BN_EPS);
            g_scale[t] = sc;
            g_shift[t] = beta[t] - mean * sc;
        }
        if (t == 0) g_ticket = 0;        // reset for next layer / replay
    }
}

// ---------------- BN apply + ReLU + residual ----------------
__global__ void k_apply() {
    int id = blockIdx.x * 256 + threadIdx.x;   // over N*16 float4s
    if (id >= NN * 16) return;
    int c = id & 15;
    float4 a = reinterpret_cast<const float4*>(g_agg)[id];
    float4 sc = reinterpret_cast<const float4*>(g_scale)[c];
    float4 sf = reinterpret_cast<const float4*>(g_shift)[c];
    float4 xv = reinterpret_cast<const float4*>(g_x)[id];
    xv.x += fmaxf(fmaf(a.x, sc.x, sf.x), 0.f);
    xv.y += fmaxf(fmaf(a.y, sc.y, sf.y), 0.f);
    xv.z += fmaxf(fmaf(a.z, sc.z, sf.z), 0.f);
    xv.w += fmaxf(fmaf(a.w, sc.w, sf.w), 0.f);
    reinterpret_cast<float4*>(g_x)[id] = xv;
}

// ------- last layer: BN apply + ReLU + residual + edge-head precompute -----
__global__ void __launch_bounds__(256) k_apply_head(const float* __restrict__ fcW) {
    __shared__ float sc[64], sf[64], Wh[256];
    int tid = threadIdx.x;
    if (tid < 64)  sc[tid] = g_scale[tid];
    else if (tid < 128) sf[tid - 64] = g_shift[tid - 64];
    for (int i = tid; i < 256; i += 256) Wh[i] = fcW[i];
    __syncthreads();
    int n = blockIdx.x * 256 + tid;
    if (n >= NN) return;
    const float4* a4 = (const float4*)(g_agg + (size_t)n * 64);
    const float4* x4 = (const float4*)(g_x   + (size_t)n * 64);
    float a0 = 0.f, a1 = 0.f, b0 = 0.f, b1 = 0.f;
    #pragma unroll
    for (int h4 = 0; h4 < 16; h4++) {
        float4 a = a4[h4];
        float4 xv = x4[h4];
        #pragma unroll
        for (int kk = 0; kk < 4; kk++) {
            int h = h4 * 4 + kk;
            float val = (&xv.x)[kk] +
                        fmaxf(fmaf((&a.x)[kk], sc[h], sf[h]), 0.f);
            a0 = fmaf(val, Wh[h * 2],            a0);
            a1 = fmaf(val, Wh[h * 2 + 1],        a1);
            b0 = fmaf(val, Wh[(64 + h) * 2],     b0);
            b1 = fmaf(val, Wh[(64 + h) * 2 + 1], b1);
        }
    }
    g_head[n] = make_float4(a0, a1, b0, b1);   // x not stored: nothing reads it
}

// ---------------- edge head: out[e] = a[src] + b[dst] + fcb -----------------
__global__ void k_final(const int* __restrict__ eio,
                        const float* __restrict__ fcb,
                        float* __restrict__ out) {
    int e = blockIdx.x * 256 + threadIdx.x;
    if (e >= EOUT) return;
    int s = eio[e];
    int d = eio[EOUT + e];
    float4 hs = g_head[s];
    float4 hd = g_head[d];
    float2 o;
    o.x = hs.x + hd.z + fcb[0];
    o.y = hs.y + hd.w + fcb[1];
    ((float2*)out)[e] = o;
}

// ---------------- launch ----------------
extern "C" void kernel_launch(void* const* d_in, const int* in_sizes, int n_in,
                              void* d_out, int out_size) {
    const float* x    = (const float*)d_in[0];
    const int*   ei   = (const int*)d_in[1];
    const int*   eio  = (const int*)d_in[2];
    const float* Wemb = (const float*)d_in[3];
    const float* bemb = (const float*)d_in[4];
    const float* convW= (const float*)d_in[5];
    const float* convb= (const float*)d_in[6];
    const float* gam  = (const float*)d_in[7];
    const float* bet  = (const float*)d_in[8];
    const float* fcW  = (const float*)d_in[9];
    const float* fcb  = (const float*)d_in[10];
    float*       out  = (float*)d_out;

    k_deg_count<<<(EE / 4 + 255) / 256, 256>>>(ei);
    k_scan1<<<SCAN_BLOCKS, 1024>>>();
    k_scan23<<<(NN + 255) / 256, 256>>>();
    k_fill<<<(EE / 4 + 255) / 256, 256>>>(ei);
    k_embed<<<GB, 256>>>(x, Wemb, bemb);

    for (int l = 0; l < 6; l++) {
        k_gather<<<(NN * 32 + 255) / 256, 256>>>();
        k_gemm<<<GB, 256>>>(convW + l * 64 * 64, convb + l * 64);
        k_stats<<<STATS_BLOCKS, 256>>>(gam + l * 64, bet + l * 64);
        if (l < 5) k_apply<<<(NN * 16 + 255) / 256, 256>>>();
        else       k_apply_head<<<GB, 256>>>(fcW);
    }

    k_final<<<(EOUT + 255) / 256, 256>>>(eio, fcb, out);
}

// round 14
// speedup vs baseline: 1.0278x; 1.0278x over previous
#include <cuda_runtime.h>
#include <cuda_bf16.h>

#define NN   100000
#define EE   1600000
#define EOUT 400000
#define HIDD 64
#define GB   ((NN + 255) / 256)
#define STATS_BLOCKS 128
#define SCAN_BLOCKS  ((NN + 1023) / 1024)
#define BN_EPS 1e-5f

typedef unsigned long long u64;

// ---------------- f32x2 packed helpers (sm_103a FFMA2 path) ----------------
__device__ __forceinline__ u64 pack2(float x) {
    u64 r; unsigned xi = __float_as_uint(x);
    asm("mov.b64 %0, {%1, %1};" : "=l"(r) : "r"(xi));
    return r;
}
__device__ __forceinline__ u64 fma2(u64 a, u64 b, u64 c) {
    u64 d;
    asm("fma.rn.f32x2 %0, %1, %2, %3;" : "=l"(d) : "l"(a), "l"(b), "l"(c));
    return d;
}
__device__ __forceinline__ u64 add2(u64 a, u64 b) {
    u64 d;
    asm("add.rn.f32x2 %0, %1, %2;" : "=l"(d) : "l"(a), "l"(b));
    return d;
}

// ---------------- scratch (device globals; zero-initialized, no alloc) -----
__device__ float g_dinv[NN];
__device__ int   g_deg[NN];          // holds EXTRA degree; reset to 0 by scan1
__device__ int   g_rowptr[NN + 1];
__device__ int   g_cursor[NN];
__device__ int   g_bsum[SCAN_BLOCKS];
__device__ int2  g_csr[EE];          // (src, norm-bits)
__device__ float g_x  [NN * HIDD];   // x_embed
__device__ float g_hw [NN * HIDD];   // aggregated x (pre-GEMM)
__device__ float g_agg[NN * HIDD];   // conv output
__device__ float g_part[STATS_BLOCKS * 128];
__device__ float g_scale[HIDD];
__device__ float g_shift[HIDD];
__device__ unsigned g_ticket;        // zero-init; last block resets
__device__ float4 g_head[NN];        // (a0,a1,b0,b1) edge-head halves

// ---------------- degree (extra degree on top of self loop) ----------------
__global__ void k_deg_count(const int* __restrict__ ei) {
    int e = blockIdx.x * 256 + threadIdx.x;
    if (e < EE) atomicAdd(&g_deg[ei[EE + e]], 1);
}

// ---------------- scan phase 1 (+ dinv fused + deg reset for next replay) --
__global__ void k_scan1() {
    __shared__ int wsum[32];
    int tid = threadIdx.x;               // 1024
    int lane = tid & 31, wid = tid >> 5;
    int i = blockIdx.x * 1024 + tid;
    int v = 0;
    if (i < NN) {
        v = g_deg[i];                    // extra degree = deg - 1
        g_deg[i] = 0;                    // reset for next graph replay
        g_dinv[i] = rsqrtf((float)(v + 1));
    }
    int incl = v;
    #pragma unroll
    for (int o = 1; o < 32; o <<= 1) {
        int t = __shfl_up_sync(0xffffffffu, incl, o);
        if (lane >= o) incl += t;
    }
    if (lane == 31) wsum[wid] = incl;
    __syncthreads();
    if (wid == 0) {
        int s = wsum[lane];
        #pragma unroll
        for (int o = 1; o < 32; o <<= 1) {
            int t = __shfl_up_sync(0xffffffffu, s, o);
            if (lane >= o) s += t;
        }
        wsum[lane] = s;
    }
    __syncthreads();
    int excl = (wid ? wsum[wid - 1] : 0) + incl - v;
    if (i < NN) g_rowptr[i] = excl;      // block-local for now
    if (tid == 1023) g_bsum[blockIdx.x] = wsum[31];   // sole writer
}

// ---- scan 2+3 + node embedding fused (independent work, same grid) --------
__global__ void __launch_bounds__(256) k_scan23_embed(
        const float* __restrict__ x,
        const float* __restrict__ W,
        const float* __restrict__ b) {
    __shared__ int sb[128];
    __shared__ __align__(16) float Ws[16 * 64];
    __shared__ __align__(16) float bs[64];
    int tid = threadIdx.x;               // 256
    // load embed weights while scan warms up
    for (int i = tid; i < 16 * 64; i += 256) Ws[i] = W[i];
    if (tid >= 64 && tid < 128) bs[tid - 64] = b[tid - 64];
    if (tid < 128) sb[tid] = (tid < SCAN_BLOCKS) ? g_bsum[tid] : 0;
    __syncthreads();
    #pragma unroll
    for (int o = 1; o < 128; o <<= 1) {
        int v = 0;
        if (tid < 128 && tid >= o) v = sb[tid - o];
        __syncthreads();
        if (tid < 128) sb[tid] += v;     // inclusive scan
        __syncthreads();
    }
    int i = blockIdx.x * 256 + tid;
    if (i < NN) {
        int bb = i >> 10;
        int off = bb ? sb[bb - 1] : 0;   // exclusive prefix
        int r = g_rowptr[i] + off;
        g_rowptr[i] = r;
        g_cursor[i] = r;
    }
    if (i == 0) g_rowptr[NN] = EE;       // sum(deg-1) == E exactly

    // ---- embed: x[N,16] @ Wemb + bemb -> g_x (independent of scan) ----
    if (i >= NN) return;
    u64 acc2[32];
    const u64* b2 = (const u64*)bs;
    #pragma unroll
    for (int h = 0; h < 32; h++) acc2[h] = b2[h];
    const float4* x4 = (const float4*)(x + (size_t)i * 16);
    #pragma unroll
    for (int k4 = 0; k4 < 4; k4++) {
        float4 xv = x4[k4];
        #pragma unroll
        for (int kk = 0; kk < 4; kk++) {
            u64 xx = pack2((&xv.x)[kk]);
            const ulonglong2* wrow = (const ulonglong2*)(Ws + (k4 * 4 + kk) * 64);
            #pragma unroll
            for (int h4 = 0; h4 < 16; h4++) {
                ulonglong2 w = wrow[h4];
                acc2[2 * h4]     = fma2(xx, w.x, acc2[2 * h4]);
                acc2[2 * h4 + 1] = fma2(xx, w.y, acc2[2 * h4 + 1]);
            }
        }
    }
    ulonglong2* o2 = (ulonglong2*)(g_x + (size_t)i * 64);
    #pragma unroll
    for (int h4 = 0; h4 < 16; h4++) {
        ulonglong2 o; o.x = acc2[2 * h4]; o.y = acc2[2 * h4 + 1];
        o2[h4] = o;
    }
}

// ---------------- CSR fill ----------------
__global__ void k_fill(const int* __restrict__ ei) {
    int e = blockIdx.x * 256 + threadIdx.x;
    if (e >= EE) return;
    int s = ei[e], d = ei[EE + e];
    int p = atomicAdd(&g_cursor[d], 1);
    g_csr[p] = make_int2(s, __float_as_int(g_dinv[s] * g_dinv[d]));
}

// ---------------- gather: hw[n] = sum nrm*x[src] + dinv^2*x[n] --------------
__global__ void k_gather() {
    int t = blockIdx.x * 256 + threadIdx.x;
    int node = t >> 5;
    if (node >= NN) return;
    int lane = t & 31;
    const float2* x2 = (const float2*)g_x;
    int beg = g_rowptr[node], end = g_rowptr[node + 1];
    float di = g_dinv[node];
    float2 acc = x2[node * 32 + lane];
    acc.x *= di * di; acc.y *= di * di;
    float2 acc2 = make_float2(0.f, 0.f);
    int i = beg;
    if ((i & 1) && i < end) {            // align to int4 boundary
        int2 a = g_csr[i];
        float2 va = x2[a.x * 32 + lane];
        float na = __int_as_float(a.y);
        acc.x = fmaf(na, va.x, acc.x); acc.y = fmaf(na, va.y, acc.y);
        i++;
    }
    for (; i + 3 < end; i += 4) {        // 4 independent gathers in flight
        int4 c0 = *(const int4*)&g_csr[i];
        int4 c1 = *(const int4*)&g_csr[i + 2];
        float2 v0 = x2[c0.x * 32 + lane];
        float2 v1 = x2[c0.z * 32 + lane];
        float2 v2 = x2[c1.x * 32 + lane];
        float2 v3 = x2[c1.z * 32 + lane];
        float n0 = __int_as_float(c0.y), n1 = __int_as_float(c0.w);
        float n2 = __int_as_float(c1.y), n3 = __int_as_float(c1.w);
        acc.x  = fmaf(n0, v0.x, acc.x);  acc.y  = fmaf(n0, v0.y, acc.y);
        acc2.x = fmaf(n1, v1.x, acc2.x); acc2.y = fmaf(n1, v1.y, acc2.y);
        acc.x  = fmaf(n2, v2.x, acc.x);  acc.y  = fmaf(n2, v2.y, acc.y);
        acc2.x = fmaf(n3, v3.x, acc2.x); acc2.y = fmaf(n3, v3.y, acc2.y);
    }
    for (; i < end; i++) {
        int2 a = g_csr[i];
        float2 va = x2[a.x * 32 + lane];
        float na = __int_as_float(a.y);
        acc.x = fmaf(na, va.x, acc.x); acc.y = fmaf(na, va.y, acc.y);
    }
    acc.x += acc2.x; acc.y += acc2.y;
    ((float2*)g_hw)[node * 32 + lane] = acc;
}

// ---------------- GEMM: agg = hw @ W + b (node per thread, f32x2) ----------
__global__ void __launch_bounds__(256) k_gemm(const float* __restrict__ W,
                                              const float* __restrict__ b) {
    __shared__ __align__(16) float Ws[64 * 64];
    __shared__ __align__(16) float bs[64];
    int tid = threadIdx.x;               // 256
    for (int i = tid; i < 64 * 64; i += 256) Ws[i] = W[i];
    if (tid < 64) bs[tid] = b[tid];
    __syncthreads();
    int n = blockIdx.x * 256 + tid;
    if (n >= NN) return;
    u64 acc2[32];
    #pragma unroll
    for (int h = 0; h < 32; h++) acc2[h] = 0ull;
    const float4* x4 = (const float4*)(g_hw + (size_t)n * 64);
    for (int k4 = 0; k4 < 16; k4++) {
        float4 xk = x4[k4];
        #pragma unroll
        for (int kk = 0; kk < 4; kk++) {
            u64 xx = pack2((&xk.x)[kk]);
            const ulonglong2* wrow = (const ulonglong2*)(Ws + (k4 * 4 + kk) * 64);
            #pragma unroll
            for (int h4 = 0; h4 < 16; h4++) {
                ulonglong2 w = wrow[h4];
                acc2[2 * h4]     = fma2(xx, w.x, acc2[2 * h4]);
                acc2[2 * h4 + 1] = fma2(xx, w.y, acc2[2 * h4 + 1]);
            }
        }
    }
    const u64* b2 = (const u64*)bs;
    ulonglong2* o2 = (ulonglong2*)(g_agg + (size_t)n * 64);
    #pragma unroll
    for (int h4 = 0; h4 < 16; h4++) {
        ulonglong2 o;
        o.x = add2(acc2[2 * h4],     b2[2 * h4]);
        o.y = add2(acc2[2 * h4 + 1], b2[2 * h4 + 1]);
        o2[h4] = o;
    }
}

// ---------------- BN stats + fused finalize (last-block ticket) -------------
__global__ void k_stats(const float* __restrict__ gamma,
                        const float* __restrict__ beta) {
    __shared__ float ss[256], sq[256];
    __shared__ float sh[128];
    __shared__ int lastflag;
    int t = threadIdx.x;                 // 256
    int f = t & 63, g = t >> 6;
    float s = 0.f, q = 0.f;
    for (int n = blockIdx.x * 4 + g; n < NN; n += STATS_BLOCKS * 4) {
        float v = g_agg[n * 64 + f];
        s += v; q = fmaf(v, v, q);
    }
    ss[t] = s; sq[t] = q;
    __syncthreads();
    if (g == 0) {
        s = ss[f] + ss[64 + f] + ss[128 + f] + ss[192 + f];
        q = sq[f] + sq[64 + f] + sq[128 + f] + sq[192 + f];
        g_part[blockIdx.x * 128 + f]      = s;
        g_part[blockIdx.x * 128 + 64 + f] = q;
    }
    __threadfence();
    if (t == 0) lastflag = (atomicAdd(&g_ticket, 1u) == STATS_BLOCKS - 1);
    __syncthreads();
    if (lastflag) {
        if (t < 128) {
            float acc = 0.f;
            #pragma unroll 4
            for (int i = 0; i < STATS_BLOCKS; i++) acc += g_part[i * 128 + t];
            sh[t] = acc;
        }
        __syncthreads();
        if (t < 64) {
            float mean = sh[t] * (1.0f / NN);
            float var  = sh[64 + t] * (1.0f / NN) - mean * mean;
            float sc   = gamma[t] * rsqrtf(var + BN_EPS);
            g_scale[t] = sc;
            g_shift[t] = beta[t] - mean * sc;
        }
        if (t == 0) g_ticket = 0;        // reset for next layer / replay
    }
}

// ---------------- BN apply + ReLU + residual ----------------
__global__ void k_apply() {
    int id = blockIdx.x * 256 + threadIdx.x;   // over N*16 float4s
    if (id >= NN * 16) return;
    int c = id & 15;
    float4 a = reinterpret_cast<const float4*>(g_agg)[id];
    float4 sc = reinterpret_cast<const float4*>(g_scale)[c];
    float4 sf = reinterpret_cast<const float4*>(g_shift)[c];
    float4 xv = reinterpret_cast<const float4*>(g_x)[id];
    xv.x += fmaxf(fmaf(a.x, sc.x, sf.x), 0.f);
    xv.y += fmaxf(fmaf(a.y, sc.y, sf.y), 0.f);
    xv.z += fmaxf(fmaf(a.z, sc.z, sf.z), 0.f);
    xv.w += fmaxf(fmaf(a.w, sc.w, sf.w), 0.f);
    reinterpret_cast<float4*>(g_x)[id] = xv;
}

// ------- last layer: BN apply + ReLU + residual + edge-head precompute -----
__global__ void __launch_bounds__(256) k_apply_head(const float* __restrict__ fcW) {
    __shared__ float sc[64], sf[64], Wh[256];
    int tid = threadIdx.x;
    if (tid < 64)  sc[tid] = g_scale[tid];
    else if (tid < 128) sf[tid - 64] = g_shift[tid - 64];
    for (int i = tid; i < 256; i += 256) Wh[i] = fcW[i];
    __syncthreads();
    int n = blockIdx.x * 256 + tid;
    if (n >= NN) return;
    const float4* a4 = (const float4*)(g_agg + (size_t)n * 64);
    const float4* x4 = (const float4*)(g_x   + (size_t)n * 64);
    float a0 = 0.f, a1 = 0.f, b0 = 0.f, b1 = 0.f;
    #pragma unroll
    for (int h4 = 0; h4 < 16; h4++) {
        float4 a = a4[h4];
        float4 xv = x4[h4];
        #pragma unroll
        for (int kk = 0; kk < 4; kk++) {
            int h = h4 * 4 + kk;
            float val = (&xv.x)[kk] +
                        fmaxf(fmaf((&a.x)[kk], sc[h], sf[h]), 0.f);
            a0 = fmaf(val, Wh[h * 2],            a0);
            a1 = fmaf(val, Wh[h * 2 + 1],        a1);
            b0 = fmaf(val, Wh[(64 + h) * 2],     b0);
            b1 = fmaf(val, Wh[(64 + h) * 2 + 1], b1);
        }
    }
    g_head[n] = make_float4(a0, a1, b0, b1);   // x not stored: nothing reads it
}

// ---------------- edge head: out[e] = a[src] + b[dst] + fcb -----------------
__global__ void k_final(const int* __restrict__ eio,
                        const float* __restrict__ fcb,
                        float* __restrict__ out) {
    int e = blockIdx.x * 256 + threadIdx.x;
    if (e >= EOUT) return;
    int s = eio[e];
    int d = eio[EOUT + e];
    float4 hs = g_head[s];
    float4 hd = g_head[d];
    float2 o;
    o.x = hs.x + hd.z + fcb[0];
    o.y = hs.y + hd.w + fcb[1];
    ((float2*)out)[e] = o;
}

// ---------------- launch ----------------
extern "C" void kernel_launch(void* const* d_in, const int* in_sizes, int n_in,
                              void* d_out, int out_size) {
    const float* x    = (const float*)d_in[0];
    const int*   ei   = (const int*)d_in[1];
    const int*   eio  = (const int*)d_in[2];
    const float* Wemb = (const float*)d_in[3];
    const float* bemb = (const float*)d_in[4];
    const float* convW= (const float*)d_in[5];
    const float* convb= (const float*)d_in[6];
    const float* gam  = (const float*)d_in[7];
    const float* bet  = (const float*)d_in[8];
    const float* fcW  = (const float*)d_in[9];
    const float* fcb  = (const float*)d_in[10];
    float*       out  = (float*)d_out;

    k_deg_count<<<(EE + 255) / 256, 256>>>(ei);
    k_scan1<<<SCAN_BLOCKS, 1024>>>();
    k_scan23_embed<<<(NN + 255) / 256, 256>>>(x, Wemb, bemb);
    k_fill<<<(EE + 255) / 256, 256>>>(ei);

    for (int l = 0; l < 6; l++) {
        k_gather<<<(NN * 32 + 255) / 256, 256>>>();
        k_gemm<<<GB, 256>>>(convW + l * 64 * 64, convb + l * 64);
        k_stats<<<STATS_BLOCKS, 256>>>(gam + l * 64, bet + l * 64);
        if (l < 5) k_apply<<<(NN * 16 + 255) / 256, 256>>>();
        else       k_apply_head<<<GB, 256>>>(fcW);
    }

    k_final<<<(EOUT + 255) / 256, 256>>>(eio, fcb, out);
}

// round 15
// speedup vs baseline: 1.0895x; 1.0601x over previous
#include <cuda_runtime.h>
#include <cuda_fp16.h>

#define NN   100000
#define EE   1600000
#define EOUT 400000
#define HIDD 64
#define GB   ((NN + 255) / 256)
#define STATS_BLOCKS 128
#define SCAN_BLOCKS  ((NN + 1023) / 1024)
#define BN_EPS 1e-5f

typedef unsigned long long u64;

// ---------------- f32x2 packed helpers (sm_103a FFMA2 path) ----------------
__device__ __forceinline__ u64 pack2(float x) {
    u64 r; unsigned xi = __float_as_uint(x);
    asm("mov.b64 %0, {%1, %1};" : "=l"(r) : "r"(xi));
    return r;
}
__device__ __forceinline__ u64 fma2(u64 a, u64 b, u64 c) {
    u64 d;
    asm("fma.rn.f32x2 %0, %1, %2, %3;" : "=l"(d) : "l"(a), "l"(b), "l"(c));
    return d;
}
__device__ __forceinline__ u64 add2(u64 a, u64 b) {
    u64 d;
    asm("add.rn.f32x2 %0, %1, %2;" : "=l"(d) : "l"(a), "l"(b));
    return d;
}
// pack two fp32 -> fp16x2 bits
__device__ __forceinline__ unsigned f2h2(float a, float b) {
    __half2 h = __floats2half2_rn(a, b);
    return *(unsigned*)&h;
}
// u64 (two packed fp32) -> fp16x2 bits
__device__ __forceinline__ unsigned u64_to_h2(u64 p) {
    float lo = __uint_as_float((unsigned)(p & 0xffffffffull));
    float hi = __uint_as_float((unsigned)(p >> 32));
    return f2h2(lo, hi);
}

// ---------------- scratch (device globals; zero-initialized, no alloc) -----
__device__ float g_dinv[NN];
__device__ int   g_deg[NN];          // holds EXTRA degree; reset to 0 by scan1
__device__ int   g_rowptr[NN + 1];
__device__ int   g_cursor[NN];
__device__ int   g_bsum[SCAN_BLOCKS];
__device__ int2  g_csr[EE];          // (src, norm-bits)
__device__ float g_x  [NN * HIDD];   // x_embed (fp32 master)
__device__ uint4 g_xh [NN * 8];      // fp16 copy of x (rows of 128 B)
__device__ float g_hw [NN * HIDD];   // aggregated x (pre-GEMM)
__device__ float g_agg[NN * HIDD];   // conv output
__device__ float g_part[STATS_BLOCKS * 128];
__device__ float g_scale[HIDD];
__device__ float g_shift[HIDD];
__device__ unsigned g_ticket;        // zero-init; last block resets
__device__ float4 g_head[NN];        // (a0,a1,b0,b1) edge-head halves

// ---------------- degree (extra degree on top of self loop) ----------------
__global__ void k_deg_count(const int* __restrict__ ei) {
    int e = blockIdx.x * 256 + threadIdx.x;
    if (e < EE) atomicAdd(&g_deg[ei[EE + e]], 1);
}

// ---------------- scan phase 1 (+ dinv fused + deg reset for next replay) --
__global__ void k_scan1() {
    __shared__ int wsum[32];
    int tid = threadIdx.x;               // 1024
    int lane = tid & 31, wid = tid >> 5;
    int i = blockIdx.x * 1024 + tid;
    int v = 0;
    if (i < NN) {
        v = g_deg[i];                    // extra degree = deg - 1
        g_deg[i] = 0;                    // reset for next graph replay
        g_dinv[i] = rsqrtf((float)(v + 1));
    }
    int incl = v;
    #pragma unroll
    for (int o = 1; o < 32; o <<= 1) {
        int t = __shfl_up_sync(0xffffffffu, incl, o);
        if (lane >= o) incl += t;
    }
    if (lane == 31) wsum[wid] = incl;
    __syncthreads();
    if (wid == 0) {
        int s = wsum[lane];
        #pragma unroll
        for (int o = 1; o < 32; o <<= 1) {
            int t = __shfl_up_sync(0xffffffffu, s, o);
            if (lane >= o) s += t;
        }
        wsum[lane] = s;
    }
    __syncthreads();
    int excl = (wid ? wsum[wid - 1] : 0) + incl - v;
    if (i < NN) g_rowptr[i] = excl;      // block-local for now
    if (tid == 1023) g_bsum[blockIdx.x] = wsum[31];   // sole writer
}

// ---- scan 2+3 + node embedding fused (independent work, same grid) --------
__global__ void __launch_bounds__(256) k_scan23_embed(
        const float* __restrict__ x,
        const float* __restrict__ W,
        const float* __restrict__ b) {
    __shared__ int sb[128];
    __shared__ __align__(16) float Ws[16 * 64];
    __shared__ __align__(16) float bs[64];
    int tid = threadIdx.x;               // 256
    for (int i = tid; i < 16 * 64; i += 256) Ws[i] = W[i];
    if (tid >= 64 && tid < 128) bs[tid - 64] = b[tid - 64];
    if (tid < 128) sb[tid] = (tid < SCAN_BLOCKS) ? g_bsum[tid] : 0;
    __syncthreads();
    #pragma unroll
    for (int o = 1; o < 128; o <<= 1) {
        int v = 0;
        if (tid < 128 && tid >= o) v = sb[tid - o];
        __syncthreads();
        if (tid < 128) sb[tid] += v;     // inclusive scan
        __syncthreads();
    }
    int i = blockIdx.x * 256 + tid;
    if (i < NN) {
        int bb = i >> 10;
        int off = bb ? sb[bb - 1] : 0;   // exclusive prefix
        int r = g_rowptr[i] + off;
        g_rowptr[i] = r;
        g_cursor[i] = r;
    }
    if (i == 0) g_rowptr[NN] = EE;       // sum(deg-1) == E exactly

    // ---- embed: x[N,16] @ Wemb + bemb -> g_x + g_xh ----
    if (i >= NN) return;
    u64 acc2[32];
    const u64* b2 = (const u64*)bs;
    #pragma unroll
    for (int h = 0; h < 32; h++) acc2[h] = b2[h];
    const float4* x4 = (const float4*)(x + (size_t)i * 16);
    #pragma unroll
    for (int k4 = 0; k4 < 4; k4++) {
        float4 xv = x4[k4];
        #pragma unroll
        for (int kk = 0; kk < 4; kk++) {
            u64 xx = pack2((&xv.x)[kk]);
            const ulonglong2* wrow = (const ulonglong2*)(Ws + (k4 * 4 + kk) * 64);
            #pragma unroll
            for (int h4 = 0; h4 < 16; h4++) {
                ulonglong2 w = wrow[h4];
                acc2[2 * h4]     = fma2(xx, w.x, acc2[2 * h4]);
                acc2[2 * h4 + 1] = fma2(xx, w.y, acc2[2 * h4 + 1]);
            }
        }
    }
    ulonglong2* o2 = (ulonglong2*)(g_x + (size_t)i * 64);
    #pragma unroll
    for (int h4 = 0; h4 < 16; h4++) {
        ulonglong2 o; o.x = acc2[2 * h4]; o.y = acc2[2 * h4 + 1];
        o2[h4] = o;
    }
    uint4* oh = g_xh + (size_t)i * 8;
    #pragma unroll
    for (int j = 0; j < 8; j++) {
        uint4 h;
        h.x = u64_to_h2(acc2[4 * j + 0]);
        h.y = u64_to_h2(acc2[4 * j + 1]);
        h.z = u64_to_h2(acc2[4 * j + 2]);
        h.w = u64_to_h2(acc2[4 * j + 3]);
        oh[j] = h;
    }
}

// ---------------- CSR fill ----------------
__global__ void k_fill(const int* __restrict__ ei) {
    int e = blockIdx.x * 256 + threadIdx.x;
    if (e >= EE) return;
    int s = ei[e], d = ei[EE + e];
    int p = atomicAdd(&g_cursor[d], 1);
    g_csr[p] = make_int2(s, __float_as_int(g_dinv[s] * g_dinv[d]));
}

// ------- gather (fp16 operand): hw[n] = sum nrm*xh[src] + dinv^2*xh[n] -----
__global__ void k_gather() {
    int t = blockIdx.x * 256 + threadIdx.x;
    int node = t >> 5;
    if (node >= NN) return;
    int lane = t & 31;
    const __half2* xh2 = (const __half2*)g_xh;
    int beg = g_rowptr[node], end = g_rowptr[node + 1];
    float di = g_dinv[node];
    float2 acc = __half22float2(xh2[node * 32 + lane]);
    acc.x *= di * di; acc.y *= di * di;
    float2 acc2 = make_float2(0.f, 0.f);
    int i = beg;
    if ((i & 1) && i < end) {            // align to int4 boundary
        int2 a = g_csr[i];
        float2 va = __half22float2(xh2[a.x * 32 + lane]);
        float na = __int_as_float(a.y);
        acc.x = fmaf(na, va.x, acc.x); acc.y = fmaf(na, va.y, acc.y);
        i++;
    }
    for (; i + 3 < end; i += 4) {        // 4 independent gathers in flight
        int4 c0 = *(const int4*)&g_csr[i];
        int4 c1 = *(const int4*)&g_csr[i + 2];
        float2 v0 = __half22float2(xh2[c0.x * 32 + lane]);
        float2 v1 = __half22float2(xh2[c0.z * 32 + lane]);
        float2 v2 = __half22float2(xh2[c1.x * 32 + lane]);
        float2 v3 = __half22float2(xh2[c1.z * 32 + lane]);
        float n0 = __int_as_float(c0.y), n1 = __int_as_float(c0.w);
        float n2 = __int_as_float(c1.y), n3 = __int_as_float(c1.w);
        acc.x  = fmaf(n0, v0.x, acc.x);  acc.y  = fmaf(n0, v0.y, acc.y);
        acc2.x = fmaf(n1, v1.x, acc2.x); acc2.y = fmaf(n1, v1.y, acc2.y);
        acc.x  = fmaf(n2, v2.x, acc.x);  acc.y  = fmaf(n2, v2.y, acc.y);
        acc2.x = fmaf(n3, v3.x, acc2.x); acc2.y = fmaf(n3, v3.y, acc2.y);
    }
    for (; i < end; i++) {
        int2 a = g_csr[i];
        float2 va = __half22float2(xh2[a.x * 32 + lane]);
        float na = __int_as_float(a.y);
        acc.x = fmaf(na, va.x, acc.x); acc.y = fmaf(na, va.y, acc.y);
    }
    acc.x += acc2.x; acc.y += acc2.y;
    ((float2*)g_hw)[node * 32 + lane] = acc;
}

// ---------------- GEMM: agg = hw @ W + b (node per thread, f32x2) ----------
__global__ void __launch_bounds__(256) k_gemm(const float* __restrict__ W,
                                              const float* __restrict__ b) {
    __shared__ __align__(16) float Ws[64 * 64];
    __shared__ __align__(16) float bs[64];
    int tid = threadIdx.x;               // 256
    for (int i = tid; i < 64 * 64; i += 256) Ws[i] = W[i];
    if (tid < 64) bs[tid] = b[tid];
    __syncthreads();
    int n = blockIdx.x * 256 + tid;
    if (n >= NN) return;
    u64 acc2[32];
    #pragma unroll
    for (int h = 0; h < 32; h++) acc2[h] = 0ull;
    const float4* x4 = (const float4*)(g_hw + (size_t)n * 64);
    for (int k4 = 0; k4 < 16; k4++) {
        float4 xk = x4[k4];
        #pragma unroll
        for (int kk = 0; kk < 4; kk++) {
            u64 xx = pack2((&xk.x)[kk]);
            const ulonglong2* wrow = (const ulonglong2*)(Ws + (k4 * 4 + kk) * 64);
            #pragma unroll
            for (int h4 = 0; h4 < 16; h4++) {
                ulonglong2 w = wrow[h4];
                acc2[2 * h4]     = fma2(xx, w.x, acc2[2 * h4]);
                acc2[2 * h4 + 1] = fma2(xx, w.y, acc2[2 * h4 + 1]);
            }
        }
    }
    const u64* b2 = (const u64*)bs;
    ulonglong2* o2 = (ulonglong2*)(g_agg + (size_t)n * 64);
    #pragma unroll
    for (int h4 = 0; h4 < 16; h4++) {
        ulonglong2 o;
        o.x = add2(acc2[2 * h4],     b2[2 * h4]);
        o.y = add2(acc2[2 * h4 + 1], b2[2 * h4 + 1]);
        o2[h4] = o;
    }
}

// ---------------- BN stats + fused finalize (last-block ticket) -------------
__global__ void k_stats(const float* __restrict__ gamma,
                        const float* __restrict__ beta) {
    __shared__ float ss[256], sq[256];
    __shared__ float sh[128];
    __shared__ int lastflag;
    int t = threadIdx.x;                 // 256
    int f = t & 63, g = t >> 6;
    float s = 0.f, q = 0.f;
    for (int n = blockIdx.x * 4 + g; n < NN; n += STATS_BLOCKS * 4) {
        float v = g_agg[n * 64 + f];
        s += v; q = fmaf(v, v, q);
    }
    ss[t] = s; sq[t] = q;
    __syncthreads();
    if (g == 0) {
        s = ss[f] + ss[64 + f] + ss[128 + f] + ss[192 + f];
        q = sq[f] + sq[64 + f] + sq[128 + f] + sq[192 + f];
        g_part[blockIdx.x * 128 + f]      = s;
        g_part[blockIdx.x * 128 + 64 + f] = q;
    }
    __threadfence();
    if (t == 0) lastflag = (atomicAdd(&g_ticket, 1u) == STATS_BLOCKS - 1);
    __syncthreads();
    if (lastflag) {
        if (t < 128) {
            float acc = 0.f;
            #pragma unroll 4
            for (int i = 0; i < STATS_BLOCKS; i++) acc += g_part[i * 128 + t];
            sh[t] = acc;
        }
        __syncthreads();
        if (t < 64) {
            float mean = sh[t] * (1.0f / NN);
            float var  = sh[64 + t] * (1.0f / NN) - mean * mean;
            float sc   = gamma[t] * rsqrtf(var + BN_EPS);
            g_scale[t] = sc;
            g_shift[t] = beta[t] - mean * sc;
        }
        if (t == 0) g_ticket = 0;        // reset for next layer / replay
    }
}

// -------- BN apply + ReLU + residual; also refresh fp16 copy ---------------
__global__ void k_apply() {
    int id = blockIdx.x * 256 + threadIdx.x;   // over N*16 float4s
    if (id >= NN * 16) return;
    int c = id & 15;
    float4 a = reinterpret_cast<const float4*>(g_agg)[id];
    float4 sc = reinterpret_cast<const float4*>(g_scale)[c];
    float4 sf = reinterpret_cast<const float4*>(g_shift)[c];
    float4 xv = reinterpret_cast<const float4*>(g_x)[id];
    xv.x += fmaxf(fmaf(a.x, sc.x, sf.x), 0.f);
    xv.y += fmaxf(fmaf(a.y, sc.y, sf.y), 0.f);
    xv.z += fmaxf(fmaf(a.z, sc.z, sf.z), 0.f);
    xv.w += fmaxf(fmaf(a.w, sc.w, sf.w), 0.f);
    reinterpret_cast<float4*>(g_x)[id] = xv;
    ((uint2*)g_xh)[id] = make_uint2(f2h2(xv.x, xv.y), f2h2(xv.z, xv.w));
}

// ------- last layer: BN apply + ReLU + residual + edge-head precompute -----
__global__ void __launch_bounds__(256) k_apply_head(const float* __restrict__ fcW) {
    __shared__ float sc[64], sf[64], Wh[256];
    int tid = threadIdx.x;
    if (tid < 64)  sc[tid] = g_scale[tid];
    else if (tid < 128) sf[tid - 64] = g_shift[tid - 64];
    for (int i = tid; i < 256; i += 256) Wh[i] = fcW[i];
    __syncthreads();
    int n = blockIdx.x * 256 + tid;
    if (n >= NN) return;
    const float4* a4 = (const float4*)(g_agg + (size_t)n * 64);
    const float4* x4 = (const float4*)(g_x   + (size_t)n * 64);
    float a0 = 0.f, a1 = 0.f, b0 = 0.f, b1 = 0.f;
    #pragma unroll
    for (int h4 = 0; h4 < 16; h4++) {
        float4 a = a4[h4];
        float4 xv = x4[h4];
        #pragma unroll
        for (int kk = 0; kk < 4; kk++) {
            int h = h4 * 4 + kk;
            float val = (&xv.x)[kk] +
                        fmaxf(fmaf((&a.x)[kk], sc[h], sf[h]), 0.f);
            a0 = fmaf(val, Wh[h * 2],            a0);
            a1 = fmaf(val, Wh[h * 2 + 1],        a1);
            b0 = fmaf(val, Wh[(64 + h) * 2],     b0);
            b1 = fmaf(val, Wh[(64 + h) * 2 + 1], b1);
        }
    }
    g_head[n] = make_float4(a0, a1, b0, b1);   // x not stored: nothing reads it
}

// ---------------- edge head: out[e] = a[src] + b[dst] + fcb -----------------
__global__ void k_final(const int* __restrict__ eio,
                        const float* __restrict__ fcb,
                        float* __restrict__ out) {
    int e = blockIdx.x * 256 + threadIdx.x;
    if (e >= EOUT) return;
    int s = eio[e];
    int d = eio[EOUT + e];
    float4 hs = g_head[s];
    float4 hd = g_head[d];
    float2 o;
    o.x = hs.x + hd.z + fcb[0];
    o.y = hs.y + hd.w + fcb[1];
    ((float2*)out)[e] = o;
}

// ---------------- launch ----------------
extern "C" void kernel_launch(void* const* d_in, const int* in_sizes, int n_in,
                              void* d_out, int out_size) {
    const float* x    = (const float*)d_in[0];
    const int*   ei   = (const int*)d_in[1];
    const int*   eio  = (const int*)d_in[2];
    const float* Wemb = (const float*)d_in[3];
    const float* bemb = (const float*)d_in[4];
    const float* convW= (const float*)d_in[5];
    const float* convb= (const float*)d_in[6];
    const float* gam  = (const float*)d_in[7];
    const float* bet  = (const float*)d_in[8];
    const float* fcW  = (const float*)d_in[9];
    const float* fcb  = (const float*)d_in[10];
    float*       out  = (float*)d_out;

    k_deg_count<<<(EE + 255) / 256, 256>>>(ei);
    k_scan1<<<SCAN_BLOCKS, 1024>>>();
    k_scan23_embed<<<(NN + 255) / 256, 256>>>(x, Wemb, bemb);
    k_fill<<<(EE + 255) / 256, 256>>>(ei);

    for (int l = 0; l < 6; l++) {
        k_gather<<<(NN * 32 + 255) / 256, 256>>>();
        k_gemm<<<GB, 256>>>(convW + l * 64 * 64, convb + l * 64);
        k_stats<<<STATS_BLOCKS, 256>>>(gam + l * 64, bet + l * 64);
        if (l < 5) k_apply<<<(NN * 16 + 255) / 256, 256>>>();
        else       k_apply_head<<<GB, 256>>>(fcW);
    }

    k_final<<<(EOUT + 255) / 256, 256>>>(eio, fcb, out);
}

// round 16
// speedup vs baseline: 1.0922x; 1.0024x over previous
#include <cuda_runtime.h>
#include <cuda_fp16.h>

#define NN   100000
#define EE   1600000
#define EOUT 400000
#define HIDD 64
#define GB   ((NN + 255) / 256)
#define STATS_BLOCKS 128
#define SCAN_BLOCKS  ((NN + 1023) / 1024)
#define BN_EPS 1e-5f

typedef unsigned long long u64;

// ---------------- f32x2 packed helpers (sm_103a FFMA2 path) ----------------
__device__ __forceinline__ u64 pack2(float x) {
    u64 r; unsigned xi = __float_as_uint(x);
    asm("mov.b64 %0, {%1, %1};" : "=l"(r) : "r"(xi));
    return r;
}
__device__ __forceinline__ u64 fma2(u64 a, u64 b, u64 c) {
    u64 d;
    asm("fma.rn.f32x2 %0, %1, %2, %3;" : "=l"(d) : "l"(a), "l"(b), "l"(c));
    return d;
}
__device__ __forceinline__ u64 add2(u64 a, u64 b) {
    u64 d;
    asm("add.rn.f32x2 %0, %1, %2;" : "=l"(d) : "l"(a), "l"(b));
    return d;
}
// pack two fp32 -> fp16x2 bits
__device__ __forceinline__ unsigned f2h2(float a, float b) {
    __half2 h = __floats2half2_rn(a, b);
    return *(unsigned*)&h;
}
// u64 (two packed fp32) -> fp16x2 bits
__device__ __forceinline__ unsigned u64_to_h2(u64 p) {
    float lo = __uint_as_float((unsigned)(p & 0xffffffffull));
    float hi = __uint_as_float((unsigned)(p >> 32));
    return f2h2(lo, hi);
}

// ---------------- scratch (device globals; zero-initialized, no alloc) -----
__device__ float g_dinv[NN];
__device__ int   g_deg[NN];          // holds EXTRA degree; reset to 0 by scan1
__device__ int   g_rowptr[NN + 1];
__device__ int   g_cursor[NN];
__device__ int   g_bsum[SCAN_BLOCKS];
__device__ int2  g_csr[EE];          // (src, norm-bits)
__device__ float g_x  [NN * HIDD];   // x_embed (fp32 master)
__device__ uint4 g_xh [NN * 8];      // fp16 copy of x (rows of 128 B)
__device__ uint4 g_hwh[NN * 8];      // fp16 aggregated x (pre-GEMM, 128 B rows)
__device__ float g_agg[NN * HIDD];   // conv output
__device__ float g_part[STATS_BLOCKS * 128];
__device__ float g_scale[HIDD];
__device__ float g_shift[HIDD];
__device__ unsigned g_ticket;        // zero-init; last block resets
__device__ float4 g_head[NN];        // (a0,a1,b0,b1) edge-head halves

// ---------------- degree (extra degree on top of self loop) ----------------
__global__ void k_deg_count(const int* __restrict__ ei) {
    int e = blockIdx.x * 256 + threadIdx.x;
    if (e < EE) atomicAdd(&g_deg[ei[EE + e]], 1);
}

// ---------------- scan phase 1 (+ dinv fused + deg reset for next replay) --
__global__ void k_scan1() {
    __shared__ int wsum[32];
    int tid = threadIdx.x;               // 1024
    int lane = tid & 31, wid = tid >> 5;
    int i = blockIdx.x * 1024 + tid;
    int v = 0;
    if (i < NN) {
        v = g_deg[i];                    // extra degree = deg - 1
        g_deg[i] = 0;                    // reset for next graph replay
        g_dinv[i] = rsqrtf((float)(v + 1));
    }
    int incl = v;
    #pragma unroll
    for (int o = 1; o < 32; o <<= 1) {
        int t = __shfl_up_sync(0xffffffffu, incl, o);
        if (lane >= o) incl += t;
    }
    if (lane == 31) wsum[wid] = incl;
    __syncthreads();
    if (wid == 0) {
        int s = wsum[lane];
        #pragma unroll
        for (int o = 1; o < 32; o <<= 1) {
            int t = __shfl_up_sync(0xffffffffu, s, o);
            if (lane >= o) s += t;
        }
        wsum[lane] = s;
    }
    __syncthreads();
    int excl = (wid ? wsum[wid - 1] : 0) + incl - v;
    if (i < NN) g_rowptr[i] = excl;      // block-local for now
    if (tid == 1023) g_bsum[blockIdx.x] = wsum[31];   // sole writer
}

// ---- scan 2+3 + node embedding fused (independent work, same grid) --------
__global__ void __launch_bounds__(256) k_scan23_embed(
        const float* __restrict__ x,
        const float* __restrict__ W,
        const float* __restrict__ b) {
    __shared__ int sb[128];
    __shared__ __align__(16) float Ws[16 * 64];
    __shared__ __align__(16) float bs[64];
    int tid = threadIdx.x;               // 256
    for (int i = tid; i < 16 * 64; i += 256) Ws[i] = W[i];
    if (tid >= 64 && tid < 128) bs[tid - 64] = b[tid - 64];
    if (tid < 128) sb[tid] = (tid < SCAN_BLOCKS) ? g_bsum[tid] : 0;
    __syncthreads();
    #pragma unroll
    for (int o = 1; o < 128; o <<= 1) {
        int v = 0;
        if (tid < 128 && tid >= o) v = sb[tid - o];
        __syncthreads();
        if (tid < 128) sb[tid] += v;     // inclusive scan
        __syncthreads();
    }
    int i = blockIdx.x * 256 + tid;
    if (i < NN) {
        int bb = i >> 10;
        int off = bb ? sb[bb - 1] : 0;   // exclusive prefix
        int r = g_rowptr[i] + off;
        g_rowptr[i] = r;
        g_cursor[i] = r;
    }
    if (i == 0) g_rowptr[NN] = EE;       // sum(deg-1) == E exactly

    // ---- embed: x[N,16] @ Wemb + bemb -> g_x + g_xh ----
    if (i >= NN) return;
    u64 acc2[32];
    const u64* b2 = (const u64*)bs;
    #pragma unroll
    for (int h = 0; h < 32; h++) acc2[h] = b2[h];
    const float4* x4 = (const float4*)(x + (size_t)i * 16);
    #pragma unroll
    for (int k4 = 0; k4 < 4; k4++) {
        float4 xv = x4[k4];
        #pragma unroll
        for (int kk = 0; kk < 4; kk++) {
            u64 xx = pack2((&xv.x)[kk]);
            const ulonglong2* wrow = (const ulonglong2*)(Ws + (k4 * 4 + kk) * 64);
            #pragma unroll
            for (int h4 = 0; h4 < 16; h4++) {
                ulonglong2 w = wrow[h4];
                acc2[2 * h4]     = fma2(xx, w.x, acc2[2 * h4]);
                acc2[2 * h4 + 1] = fma2(xx, w.y, acc2[2 * h4 + 1]);
            }
        }
    }
    ulonglong2* o2 = (ulonglong2*)(g_x + (size_t)i * 64);
    #pragma unroll
    for (int h4 = 0; h4 < 16; h4++) {
        ulonglong2 o; o.x = acc2[2 * h4]; o.y = acc2[2 * h4 + 1];
        o2[h4] = o;
    }
    uint4* oh = g_xh + (size_t)i * 8;
    #pragma unroll
    for (int j = 0; j < 8; j++) {
        uint4 h;
        h.x = u64_to_h2(acc2[4 * j + 0]);
        h.y = u64_to_h2(acc2[4 * j + 1]);
        h.z = u64_to_h2(acc2[4 * j + 2]);
        h.w = u64_to_h2(acc2[4 * j + 3]);
        oh[j] = h;
    }
}

// ---------------- CSR fill ----------------
__global__ void k_fill(const int* __restrict__ ei) {
    int e = blockIdx.x * 256 + threadIdx.x;
    if (e >= EE) return;
    int s = ei[e], d = ei[EE + e];
    int p = atomicAdd(&g_cursor[d], 1);
    g_csr[p] = make_int2(s, __float_as_int(g_dinv[s] * g_dinv[d]));
}

// ------- gather (fp16 in AND out): hwh[n] = sum nrm*xh[src] + dinv^2*xh[n] --
__global__ void k_gather() {
    int t = blockIdx.x * 256 + threadIdx.x;
    int node = t >> 5;
    if (node >= NN) return;
    int lane = t & 31;
    const __half2* xh2 = (const __half2*)g_xh;
    int beg = g_rowptr[node], end = g_rowptr[node + 1];
    float di = g_dinv[node];
    float2 acc = __half22float2(xh2[node * 32 + lane]);
    acc.x *= di * di; acc.y *= di * di;
    float2 acc2 = make_float2(0.f, 0.f);
    int i = beg;
    if ((i & 1) && i < end) {            // align to int4 boundary
        int2 a = g_csr[i];
        float2 va = __half22float2(xh2[a.x * 32 + lane]);
        float na = __int_as_float(a.y);
        acc.x = fmaf(na, va.x, acc.x); acc.y = fmaf(na, va.y, acc.y);
        i++;
    }
    for (; i + 3 < end; i += 4) {        // 4 independent gathers in flight
        int4 c0 = *(const int4*)&g_csr[i];
        int4 c1 = *(const int4*)&g_csr[i + 2];
        float2 v0 = __half22float2(xh2[c0.x * 32 + lane]);
        float2 v1 = __half22float2(xh2[c0.z * 32 + lane]);
        float2 v2 = __half22float2(xh2[c1.x * 32 + lane]);
        float2 v3 = __half22float2(xh2[c1.z * 32 + lane]);
        float n0 = __int_as_float(c0.y), n1 = __int_as_float(c0.w);
        float n2 = __int_as_float(c1.y), n3 = __int_as_float(c1.w);
        acc.x  = fmaf(n0, v0.x, acc.x);  acc.y  = fmaf(n0, v0.y, acc.y);
        acc2.x = fmaf(n1, v1.x, acc2.x); acc2.y = fmaf(n1, v1.y, acc2.y);
        acc.x  = fmaf(n2, v2.x, acc.x);  acc.y  = fmaf(n2, v2.y, acc.y);
        acc2.x = fmaf(n3, v3.x, acc2.x); acc2.y = fmaf(n3, v3.y, acc2.y);
    }
    for (; i < end; i++) {
        int2 a = g_csr[i];
        float2 va = __half22float2(xh2[a.x * 32 + lane]);
        float na = __int_as_float(a.y);
        acc.x = fmaf(na, va.x, acc.x); acc.y = fmaf(na, va.y, acc.y);
    }
    acc.x += acc2.x; acc.y += acc2.y;
    ((unsigned*)g_hwh)[node * 32 + lane] = f2h2(acc.x, acc.y);
}

// ------- GEMM: agg = hwh(fp16) @ W + b (node per thread, f32x2) ------------
__global__ void __launch_bounds__(256) k_gemm(const float* __restrict__ W,
                                              const float* __restrict__ b) {
    __shared__ __align__(16) float Ws[64 * 64];
    __shared__ __align__(16) float bs[64];
    int tid = threadIdx.x;               // 256
    for (int i = tid; i < 64 * 64; i += 256) Ws[i] = W[i];
    if (tid < 64) bs[tid] = b[tid];
    __syncthreads();
    int n = blockIdx.x * 256 + tid;
    if (n >= NN) return;
    u64 acc2[32];
    #pragma unroll
    for (int h = 0; h < 32; h++) acc2[h] = 0ull;
    const uint4* xv4 = (const uint4*)(g_hwh + (size_t)n * 8);
    #pragma unroll 2
    for (int v = 0; v < 8; v++) {        // 8 uint4 = 64 halfs (k = v*8 .. v*8+7)
        uint4 hv = xv4[v];
        #pragma unroll
        for (int j = 0; j < 4; j++) {    // each uint = 2 k-values
            unsigned u = (&hv.x)[j];
            float2 f = __half22float2(*(__half2*)&u);
            int k0 = v * 8 + j * 2;
            u64 xx0 = pack2(f.x);
            u64 xx1 = pack2(f.y);
            const ulonglong2* w0 = (const ulonglong2*)(Ws + k0 * 64);
            const ulonglong2* w1 = (const ulonglong2*)(Ws + (k0 + 1) * 64);
            #pragma unroll
            for (int h4 = 0; h4 < 16; h4++) {
                ulonglong2 wa = w0[h4];
                ulonglong2 wb = w1[h4];
                acc2[2 * h4]     = fma2(xx0, wa.x, acc2[2 * h4]);
                acc2[2 * h4 + 1] = fma2(xx0, wa.y, acc2[2 * h4 + 1]);
                acc2[2 * h4]     = fma2(xx1, wb.x, acc2[2 * h4]);
                acc2[2 * h4 + 1] = fma2(xx1, wb.y, acc2[2 * h4 + 1]);
            }
        }
    }
    const u64* b2 = (const u64*)bs;
    ulonglong2* o2 = (ulonglong2*)(g_agg + (size_t)n * 64);
    #pragma unroll
    for (int h4 = 0; h4 < 16; h4++) {
        ulonglong2 o;
        o.x = add2(acc2[2 * h4],     b2[2 * h4]);
        o.y = add2(acc2[2 * h4 + 1], b2[2 * h4 + 1]);
        o2[h4] = o;
    }
}

// ---------------- BN stats + fused finalize (last-block ticket) -------------
__global__ void k_stats(const float* __restrict__ gamma,
                        const float* __restrict__ beta) {
    __shared__ float ss[256], sq[256];
    __shared__ float sh[128];
    __shared__ int lastflag;
    int t = threadIdx.x;                 // 256
    int f = t & 63, g = t >> 6;
    float s = 0.f, q = 0.f;
    for (int n = blockIdx.x * 4 + g; n < NN; n += STATS_BLOCKS * 4) {
        float v = g_agg[n * 64 + f];
        s += v; q = fmaf(v, v, q);
    }
    ss[t] = s; sq[t] = q;
    __syncthreads();
    if (g == 0) {
        s = ss[f] + ss[64 + f] + ss[128 + f] + ss[192 + f];
        q = sq[f] + sq[64 + f] + sq[128 + f] + sq[192 + f];
        g_part[blockIdx.x * 128 + f]      = s;
        g_part[blockIdx.x * 128 + 64 + f] = q;
    }
    __threadfence();
    if (t == 0) lastflag = (atomicAdd(&g_ticket, 1u) == STATS_BLOCKS - 1);
    __syncthreads();
    if (lastflag) {
        if (t < 128) {
            float acc = 0.f;
            #pragma unroll 4
            for (int i = 0; i < STATS_BLOCKS; i++) acc += g_part[i * 128 + t];
            sh[t] = acc;
        }
        __syncthreads();
        if (t < 64) {
            float mean = sh[t] * (1.0f / NN);
            float var  = sh[64 + t] * (1.0f / NN) - mean * mean;
            float sc   = gamma[t] * rsqrtf(var + BN_EPS);
            g_scale[t] = sc;
            g_shift[t] = beta[t] - mean * sc;
        }
        if (t == 0) g_ticket = 0;        // reset for next layer / replay
    }
}

// -------- BN apply + ReLU + residual; also refresh fp16 copy ---------------
__global__ void k_apply() {
    int id = blockIdx.x * 256 + threadIdx.x;   // over N*16 float4s
    if (id >= NN * 16) return;
    int c = id & 15;
    float4 a = reinterpret_cast<const float4*>(g_agg)[id];
    float4 sc = reinterpret_cast<const float4*>(g_scale)[c];
    float4 sf = reinterpret_cast<const float4*>(g_shift)[c];
    float4 xv = reinterpret_cast<const float4*>(g_x)[id];
    xv.x += fmaxf(fmaf(a.x, sc.x, sf.x), 0.f);
    xv.y += fmaxf(fmaf(a.y, sc.y, sf.y), 0.f);
    xv.z += fmaxf(fmaf(a.z, sc.z, sf.z), 0.f);
    xv.w += fmaxf(fmaf(a.w, sc.w, sf.w), 0.f);
    reinterpret_cast<float4*>(g_x)[id] = xv;
    ((uint2*)g_xh)[id] = make_uint2(f2h2(xv.x, xv.y), f2h2(xv.z, xv.w));
}

// ------- last layer: BN apply + ReLU + residual + edge-head precompute -----
__global__ void __launch_bounds__(256) k_apply_head(const float* __restrict__ fcW) {
    __shared__ float sc[64], sf[64], Wh[256];
    int tid = threadIdx.x;
    if (tid < 64)  sc[tid] = g_scale[tid];
    else if (tid < 128) sf[tid - 64] = g_shift[tid - 64];
    for (int i = tid; i < 256; i += 256) Wh[i] = fcW[i];
    __syncthreads();
    int n = blockIdx.x * 256 + tid;
    if (n >= NN) return;
    const float4* a4 = (const float4*)(g_agg + (size_t)n * 64);
    const float4* x4 = (const float4*)(g_x   + (size_t)n * 64);
    float a0 = 0.f, a1 = 0.f, b0 = 0.f, b1 = 0.f;
    #pragma unroll
    for (int h4 = 0; h4 < 16; h4++) {
        float4 a = a4[h4];
        float4 xv = x4[h4];
        #pragma unroll
        for (int kk = 0; kk < 4; kk++) {
            int h = h4 * 4 + kk;
            float val = (&xv.x)[kk] +
                        fmaxf(fmaf((&a.x)[kk], sc[h], sf[h]), 0.f);
            a0 = fmaf(val, Wh[h * 2],            a0);
            a1 = fmaf(val, Wh[h * 2 + 1],        a1);
            b0 = fmaf(val, Wh[(64 + h) * 2],     b0);
            b1 = fmaf(val, Wh[(64 + h) * 2 + 1], b1);
        }
    }
    g_head[n] = make_float4(a0, a1, b0, b1);   // x not stored: nothing reads it
}

// ---------------- edge head: out[e] = a[src] + b[dst] + fcb -----------------
__global__ void k_final(const int* __restrict__ eio,
                        const float* __restrict__ fcb,
                        float* __restrict__ out) {
    int e = blockIdx.x * 256 + threadIdx.x;
    if (e >= EOUT) return;
    int s = eio[e];
    int d = eio[EOUT + e];
    float4 hs = g_head[s];
    float4 hd = g_head[d];
    float2 o;
    o.x = hs.x + hd.z + fcb[0];
    o.y = hs.y + hd.w + fcb[1];
    ((float2*)out)[e] = o;
}

// ---------------- launch ----------------
extern "C" void kernel_launch(void* const* d_in, const int* in_sizes, int n_in,
                              void* d_out, int out_size) {
    const float* x    = (const float*)d_in[0];
    const int*   ei   = (const int*)d_in[1];
    const int*   eio  = (const int*)d_in[2];
    const float* Wemb = (const float*)d_in[3];
    const float* bemb = (const float*)d_in[4];
    const float* convW= (const float*)d_in[5];
    const float* convb= (const float*)d_in[6];
    const float* gam  = (const float*)d_in[7];
    const float* bet  = (const float*)d_in[8];
    const float* fcW  = (const float*)d_in[9];
    const float* fcb  = (const float*)d_in[10];
    float*       out  = (float*)d_out;

    k_deg_count<<<(EE + 255) / 256, 256>>>(ei);
    k_scan1<<<SCAN_BLOCKS, 1024>>>();
    k_scan23_embed<<<(NN + 255) / 256, 256>>>(x, Wemb, bemb);
    k_fill<<<(EE + 255) / 256, 256>>>(ei);

    for (int l = 0; l < 6; l++) {
        k_gather<<<(NN * 32 + 255) / 256, 256>>>();
        k_gemm<<<GB, 256>>>(convW + l * 64 * 64, convb + l * 64);
        k_stats<<<STATS_BLOCKS, 256>>>(gam + l * 64, bet + l * 64);
        if (l < 5) k_apply<<<(NN * 16 + 255) / 256, 256>>>();
        else       k_apply_head<<<GB, 256>>>(fcW);
    }

    k_final<<<(EOUT + 255) / 256, 256>>>(eio, fcb, out);
}

// round 17
// speedup vs baseline: 1.0960x; 1.0035x over previous
#include <cuda_runtime.h>
#include <cuda_fp16.h>

#define NN   100000
#define EE   1600000
#define EOUT 400000
#define HIDD 64
#define GB   ((NN + 255) / 256)
#define STATS_BLOCKS 128
#define SCAN_BLOCKS  ((NN + 1023) / 1024)
#define BN_EPS 1e-5f

typedef unsigned long long u64;

// ---------------- f32x2 packed helpers (sm_103a FFMA2 path) ----------------
__device__ __forceinline__ u64 pack2(float x) {
    u64 r; unsigned xi = __float_as_uint(x);
    asm("mov.b64 %0, {%1, %1};" : "=l"(r) : "r"(xi));
    return r;
}
__device__ __forceinline__ u64 fma2(u64 a, u64 b, u64 c) {
    u64 d;
    asm("fma.rn.f32x2 %0, %1, %2, %3;" : "=l"(d) : "l"(a), "l"(b), "l"(c));
    return d;
}
__device__ __forceinline__ u64 add2(u64 a, u64 b) {
    u64 d;
    asm("add.rn.f32x2 %0, %1, %2;" : "=l"(d) : "l"(a), "l"(b));
    return d;
}
// pack two fp32 -> fp16x2 bits
__device__ __forceinline__ unsigned f2h2(float a, float b) {
    __half2 h = __floats2half2_rn(a, b);
    return *(unsigned*)&h;
}
// u64 (two packed fp32) -> fp16x2 bits
__device__ __forceinline__ unsigned u64_to_h2(u64 p) {
    float lo = __uint_as_float((unsigned)(p & 0xffffffffull));
    float hi = __uint_as_float((unsigned)(p >> 32));
    return f2h2(lo, hi);
}

// ---------------- scratch (device globals; zero-initialized, no alloc) -----
__device__ float g_dinv[NN];
__device__ int   g_deg[NN];          // holds EXTRA degree; reset to 0 by scan1
__device__ int   g_rowptr[NN + 1];
__device__ int   g_cursor[NN];
__device__ int   g_bsum[SCAN_BLOCKS];
__device__ int2  g_csr[EE];          // (src, norm-bits)
__device__ float g_x  [NN * HIDD];   // x_embed (fp32 master)
__device__ uint4 g_xh [NN * 8];      // fp16 copy of x (rows of 128 B)
__device__ uint4 g_hwh[NN * 8];      // fp16 aggregated x (pre-GEMM, 128 B rows)
__device__ float g_agg[NN * HIDD];   // conv output
__device__ float g_part[STATS_BLOCKS * 128];
__device__ float g_scale[HIDD];
__device__ float g_shift[HIDD];
__device__ unsigned g_ticket;        // zero-init; last block resets
__device__ float4 g_head[NN];        // (a0,a1,b0,b1) edge-head halves

// ---------------- degree (extra degree on top of self loop) ----------------
__global__ void k_deg_count(const int* __restrict__ ei) {
    int e = blockIdx.x * 256 + threadIdx.x;
    if (e < EE) atomicAdd(&g_deg[ei[EE + e]], 1);
}

// ---------------- scan phase 1 (+ dinv fused + deg reset for next replay) --
__global__ void k_scan1() {
    __shared__ int wsum[32];
    int tid = threadIdx.x;               // 1024
    int lane = tid & 31, wid = tid >> 5;
    int i = blockIdx.x * 1024 + tid;
    int v = 0;
    if (i < NN) {
        v = g_deg[i];                    // extra degree = deg - 1
        g_deg[i] = 0;                    // reset for next graph replay
        g_dinv[i] = rsqrtf((float)(v + 1));
    }
    int incl = v;
    #pragma unroll
    for (int o = 1; o < 32; o <<= 1) {
        int t = __shfl_up_sync(0xffffffffu, incl, o);
        if (lane >= o) incl += t;
    }
    if (lane == 31) wsum[wid] = incl;
    __syncthreads();
    if (wid == 0) {
        int s = wsum[lane];
        #pragma unroll
        for (int o = 1; o < 32; o <<= 1) {
            int t = __shfl_up_sync(0xffffffffu, s, o);
            if (lane >= o) s += t;
        }
        wsum[lane] = s;
    }
    __syncthreads();
    int excl = (wid ? wsum[wid - 1] : 0) + incl - v;
    if (i < NN) g_rowptr[i] = excl;      // block-local for now
    if (tid == 1023) g_bsum[blockIdx.x] = wsum[31];   // sole writer
}

// ---- scan 2+3 + node embedding fused (independent work, same grid) --------
__global__ void __launch_bounds__(256) k_scan23_embed(
        const float* __restrict__ x,
        const float* __restrict__ W,
        const float* __restrict__ b) {
    __shared__ int sb[128];
    __shared__ __align__(16) float Ws[16 * 64];
    __shared__ __align__(16) float bs[64];
    int tid = threadIdx.x;               // 256
    for (int i = tid; i < 16 * 64; i += 256) Ws[i] = W[i];
    if (tid >= 64 && tid < 128) bs[tid - 64] = b[tid - 64];
    if (tid < 128) sb[tid] = (tid < SCAN_BLOCKS) ? g_bsum[tid] : 0;
    __syncthreads();
    #pragma unroll
    for (int o = 1; o < 128; o <<= 1) {
        int v = 0;
        if (tid < 128 && tid >= o) v = sb[tid - o];
        __syncthreads();
        if (tid < 128) sb[tid] += v;     // inclusive scan
        __syncthreads();
    }
    int i = blockIdx.x * 256 + tid;
    if (i < NN) {
        int bb = i >> 10;
        int off = bb ? sb[bb - 1] : 0;   // exclusive prefix
        int r = g_rowptr[i] + off;
        g_rowptr[i] = r;
        g_cursor[i] = r;
    }
    if (i == 0) g_rowptr[NN] = EE;       // sum(deg-1) == E exactly

    // ---- embed: x[N,16] @ Wemb + bemb -> g_x + g_xh ----
    if (i >= NN) return;
    u64 acc2[32];
    const u64* b2 = (const u64*)bs;
    #pragma unroll
    for (int h = 0; h < 32; h++) acc2[h] = b2[h];
    const float4* x4 = (const float4*)(x + (size_t)i * 16);
    #pragma unroll
    for (int k4 = 0; k4 < 4; k4++) {
        float4 xv = x4[k4];
        #pragma unroll
        for (int kk = 0; kk < 4; kk++) {
            u64 xx = pack2((&xv.x)[kk]);
            const ulonglong2* wrow = (const ulonglong2*)(Ws + (k4 * 4 + kk) * 64);
            #pragma unroll
            for (int h4 = 0; h4 < 16; h4++) {
                ulonglong2 w = wrow[h4];
                acc2[2 * h4]     = fma2(xx, w.x, acc2[2 * h4]);
                acc2[2 * h4 + 1] = fma2(xx, w.y, acc2[2 * h4 + 1]);
            }
        }
    }
    ulonglong2* o2 = (ulonglong2*)(g_x + (size_t)i * 64);
    #pragma unroll
    for (int h4 = 0; h4 < 16; h4++) {
        ulonglong2 o; o.x = acc2[2 * h4]; o.y = acc2[2 * h4 + 1];
        o2[h4] = o;
    }
    uint4* oh = g_xh + (size_t)i * 8;
    #pragma unroll
    for (int j = 0; j < 8; j++) {
        uint4 h;
        h.x = u64_to_h2(acc2[4 * j + 0]);
        h.y = u64_to_h2(acc2[4 * j + 1]);
        h.z = u64_to_h2(acc2[4 * j + 2]);
        h.w = u64_to_h2(acc2[4 * j + 3]);
        oh[j] = h;
    }
}

// ---------------- CSR fill ----------------
__global__ void k_fill(const int* __restrict__ ei) {
    int e = blockIdx.x * 256 + threadIdx.x;
    if (e >= EE) return;
    int s = ei[e], d = ei[EE + e];
    int p = atomicAdd(&g_cursor[d], 1);
    g_csr[p] = make_int2(s, __float_as_int(g_dinv[s] * g_dinv[d]));
}

// ------- gather (fp16 in AND out): hwh[n] = sum nrm*xh[src] + dinv^2*xh[n] --
__global__ void k_gather() {
    int t = blockIdx.x * 256 + threadIdx.x;
    int node = t >> 5;
    if (node >= NN) return;
    int lane = t & 31;
    const __half2* xh2 = (const __half2*)g_xh;
    int beg = g_rowptr[node], end = g_rowptr[node + 1];
    float di = g_dinv[node];
    float2 acc = __half22float2(xh2[node * 32 + lane]);
    acc.x *= di * di; acc.y *= di * di;
    float2 acc2 = make_float2(0.f, 0.f);
    int i = beg;
    if ((i & 1) && i < end) {            // align to int4 boundary
        int2 a = g_csr[i];
        float2 va = __half22float2(xh2[a.x * 32 + lane]);
        float na = __int_as_float(a.y);
        acc.x = fmaf(na, va.x, acc.x); acc.y = fmaf(na, va.y, acc.y);
        i++;
    }
    for (; i + 3 < end; i += 4) {        // 4 independent gathers in flight
        int4 c0 = *(const int4*)&g_csr[i];
        int4 c1 = *(const int4*)&g_csr[i + 2];
        float2 v0 = __half22float2(xh2[c0.x * 32 + lane]);
        float2 v1 = __half22float2(xh2[c0.z * 32 + lane]);
        float2 v2 = __half22float2(xh2[c1.x * 32 + lane]);
        float2 v3 = __half22float2(xh2[c1.z * 32 + lane]);
        float n0 = __int_as_float(c0.y), n1 = __int_as_float(c0.w);
        float n2 = __int_as_float(c1.y), n3 = __int_as_float(c1.w);
        acc.x  = fmaf(n0, v0.x, acc.x);  acc.y  = fmaf(n0, v0.y, acc.y);
        acc2.x = fmaf(n1, v1.x, acc2.x); acc2.y = fmaf(n1, v1.y, acc2.y);
        acc.x  = fmaf(n2, v2.x, acc.x);  acc.y  = fmaf(n2, v2.y, acc.y);
        acc2.x = fmaf(n3, v3.x, acc2.x); acc2.y = fmaf(n3, v3.y, acc2.y);
    }
    for (; i < end; i++) {
        int2 a = g_csr[i];
        float2 va = __half22float2(xh2[a.x * 32 + lane]);
        float na = __int_as_float(a.y);
        acc.x = fmaf(na, va.x, acc.x); acc.y = fmaf(na, va.y, acc.y);
    }
    acc.x += acc2.x; acc.y += acc2.y;
    ((unsigned*)g_hwh)[node * 32 + lane] = f2h2(acc.x, acc.y);
}

// ------- GEMM: agg = hwh(fp16) @ W + b (node per thread, f32x2) ------------
__global__ void __launch_bounds__(256) k_gemm(const float* __restrict__ W,
                                              const float* __restrict__ b) {
    __shared__ __align__(16) float Ws[64 * 64];
    __shared__ __align__(16) float bs[64];
    int tid = threadIdx.x;               // 256
    for (int i = tid; i < 64 * 64; i += 256) Ws[i] = W[i];
    if (tid < 64) bs[tid] = b[tid];
    __syncthreads();
    int n = blockIdx.x * 256 + tid;
    if (n >= NN) return;
    u64 acc2[32];
    #pragma unroll
    for (int h = 0; h < 32; h++) acc2[h] = 0ull;
    const uint4* xv4 = (const uint4*)(g_hwh + (size_t)n * 8);
    #pragma unroll 2
    for (int v = 0; v < 8; v++) {        // 8 uint4 = 64 halfs (k = v*8 .. v*8+7)
        uint4 hv = xv4[v];
        #pragma unroll
        for (int j = 0; j < 4; j++) {    // each uint = 2 k-values
            unsigned u = (&hv.x)[j];
            float2 f = __half22float2(*(__half2*)&u);
            int k0 = v * 8 + j * 2;
            u64 xx0 = pack2(f.x);
            u64 xx1 = pack2(f.y);
            const ulonglong2* w0 = (const ulonglong2*)(Ws + k0 * 64);
            const ulonglong2* w1 = (const ulonglong2*)(Ws + (k0 + 1) * 64);
            #pragma unroll
            for (int h4 = 0; h4 < 16; h4++) {
                ulonglong2 wa = w0[h4];
                ulonglong2 wb = w1[h4];
                acc2[2 * h4]     = fma2(xx0, wa.x, acc2[2 * h4]);
                acc2[2 * h4 + 1] = fma2(xx0, wa.y, acc2[2 * h4 + 1]);
                acc2[2 * h4]     = fma2(xx1, wb.x, acc2[2 * h4]);
                acc2[2 * h4 + 1] = fma2(xx1, wb.y, acc2[2 * h4 + 1]);
            }
        }
    }
    const u64* b2 = (const u64*)bs;
    ulonglong2* o2 = (ulonglong2*)(g_agg + (size_t)n * 64);
    #pragma unroll
    for (int h4 = 0; h4 < 16; h4++) {
        ulonglong2 o;
        o.x = add2(acc2[2 * h4],     b2[2 * h4]);
        o.y = add2(acc2[2 * h4 + 1], b2[2 * h4 + 1]);
        o2[h4] = o;
    }
}

// ---------------- BN stats + fused finalize (last-block ticket) -------------
__global__ void k_stats(const float* __restrict__ gamma,
                        const float* __restrict__ beta) {
    __shared__ float ss[256], sq[256];
    __shared__ float sh[128];
    __shared__ int lastflag;
    int t = threadIdx.x;                 // 256
    int f = t & 63, g = t >> 6;
    float s = 0.f, q = 0.f;
    for (int n = blockIdx.x * 4 + g; n < NN; n += STATS_BLOCKS * 4) {
        float v = g_agg[n * 64 + f];
        s += v; q = fmaf(v, v, q);
    }
    ss[t] = s; sq[t] = q;
    __syncthreads();
    if (g == 0) {
        s = ss[f] + ss[64 + f] + ss[128 + f] + ss[192 + f];
        q = sq[f] + sq[64 + f] + sq[128 + f] + sq[192 + f];
        g_part[blockIdx.x * 128 + f]      = s;
        g_part[blockIdx.x * 128 + 64 + f] = q;
    }
    __threadfence();
    if (t == 0) lastflag = (atomicAdd(&g_ticket, 1u) == STATS_BLOCKS - 1);
    __syncthreads();
    if (lastflag) {
        if (t < 128) {
            float acc = 0.f;
            #pragma unroll 4
            for (int i = 0; i < STATS_BLOCKS; i++) acc += g_part[i * 128 + t];
            sh[t] = acc;
        }
        __syncthreads();
        if (t < 64) {
            float mean = sh[t] * (1.0f / NN);
            float var  = sh[64 + t] * (1.0f / NN) - mean * mean;
            float sc   = gamma[t] * rsqrtf(var + BN_EPS);
            g_scale[t] = sc;
            g_shift[t] = beta[t] - mean * sc;
        }
        if (t == 0) g_ticket = 0;        // reset for next layer / replay
    }
}

// -------- BN apply + ReLU + residual; also refresh fp16 copy ---------------
__global__ void k_apply() {
    int id = blockIdx.x * 256 + threadIdx.x;   // over N*16 float4s
    if (id >= NN * 16) return;
    int c = id & 15;
    float4 a = reinterpret_cast<const float4*>(g_agg)[id];
    float4 sc = reinterpret_cast<const float4*>(g_scale)[c];
    float4 sf = reinterpret_cast<const float4*>(g_shift)[c];
    float4 xv = reinterpret_cast<const float4*>(g_x)[id];
    xv.x += fmaxf(fmaf(a.x, sc.x, sf.x), 0.f);
    xv.y += fmaxf(fmaf(a.y, sc.y, sf.y), 0.f);
    xv.z += fmaxf(fmaf(a.z, sc.z, sf.z), 0.f);
    xv.w += fmaxf(fmaf(a.w, sc.w, sf.w), 0.f);
    reinterpret_cast<float4*>(g_x)[id] = xv;
    ((uint2*)g_xh)[id] = make_uint2(f2h2(xv.x, xv.y), f2h2(xv.z, xv.w));
}

// ------- last layer: BN apply + ReLU + residual + edge-head precompute -----
__global__ void __launch_bounds__(256) k_apply_head(const float* __restrict__ fcW) {
    __shared__ float sc[64], sf[64], Wh[256];
    int tid = threadIdx.x;
    if (tid < 64)  sc[tid] = g_scale[tid];
    else if (tid < 128) sf[tid - 64] = g_shift[tid - 64];
    for (int i = tid; i < 256; i += 256) Wh[i] = fcW[i];
    __syncthreads();
    int n = blockIdx.x * 256 + tid;
    if (n >= NN) return;
    const float4* a4 = (const float4*)(g_agg + (size_t)n * 64);
    const float4* x4 = (const float4*)(g_x   + (size_t)n * 64);
    float a0 = 0.f, a1 = 0.f, b0 = 0.f, b1 = 0.f;
    #pragma unroll
    for (int h4 = 0; h4 < 16; h4++) {
        float4 a = a4[h4];
        float4 xv = x4[h4];
        #pragma unroll
        for (int kk = 0; kk < 4; kk++) {
            int h = h4 * 4 + kk;
            float val = (&xv.x)[kk] +
                        fmaxf(fmaf((&a.x)[kk], sc[h], sf[h]), 0.f);
            a0 = fmaf(val, Wh[h * 2],            a0);
            a1 = fmaf(val, Wh[h * 2 + 1],        a1);
            b0 = fmaf(val, Wh[(64 + h) * 2],     b0);
            b1 = fmaf(val, Wh[(64 + h) * 2 + 1], b1);
        }
    }
    g_head[n] = make_float4(a0, a1, b0, b1);   // x not stored: nothing reads it
}

// ---------------- edge head: out[e] = a[src] + b[dst] + fcb -----------------
__global__ void k_final(const int* __restrict__ eio,
                        const float* __restrict__ fcb,
                        float* __restrict__ out) {
    int e = blockIdx.x * 256 + threadIdx.x;
    if (e >= EOUT) return;
    int s = eio[e];
    int d = eio[EOUT + e];
    float4 hs = g_head[s];
    float4 hd = g_head[d];
    float2 o;
    o.x = hs.x + hd.z + fcb[0];
    o.y = hs.y + hd.w + fcb[1];
    ((float2*)out)[e] = o;
}

// ---------------- launch ----------------
extern "C" void kernel_launch(void* const* d_in, const int* in_sizes, int n_in,
                              void* d_out, int out_size) {
    const float* x    = (const float*)d_in[0];
    const int*   ei   = (const int*)d_in[1];
    const int*   eio  = (const int*)d_in[2];
    const float* Wemb = (const float*)d_in[3];
    const float* bemb = (const float*)d_in[4];
    const float* convW= (const float*)d_in[5];
    const float* convb= (const float*)d_in[6];
    const float* gam  = (const float*)d_in[7];
    const float* bet  = (const float*)d_in[8];
    const float* fcW  = (const float*)d_in[9];
    const float* fcb  = (const float*)d_in[10];
    float*       out  = (float*)d_out;

    k_deg_count<<<(EE + 255) / 256, 256>>>(ei);
    k_scan1<<<SCAN_BLOCKS, 1024>>>();
    k_scan23_embed<<<(NN + 255) / 256, 256>>>(x, Wemb, bemb);
    k_fill<<<(EE + 255) / 256, 256>>>(ei);

    for (int l = 0; l < 6; l++) {
        k_gather<<<(NN * 32 + 255) / 256, 256>>>();
        k_gemm<<<GB, 256>>>(convW + l * 64 * 64, convb + l * 64);
        k_stats<<<STATS_BLOCKS, 256>>>(gam + l * 64, bet + l * 64);
        if (l < 5) k_apply<<<(NN * 16 + 255) / 256, 256>>>();
        else       k_apply_head<<<GB, 256>>>(fcW);
    }

    k_final<<<(EOUT + 255) / 256, 256>>>(eio, fcb, out);
}